// round 2
// baseline (speedup 1.0000x reference)
#include <cuda_runtime.h>
#include <math.h>

// Problem constants
#define BB 64
#define NN 8732
#define CC 21
#define KCAND 200
#define MAXPC 20
#define MAXTOT 20

// Scratch (static device globals: allowed; no runtime allocation)
__device__ float4        g_boxes[BB * NN];          // decoded boxes per (b,n)
__device__ unsigned char g_mask[BB * NN];           // argmax != 0
__device__ float         g_cls_scores[BB * CC * MAXPC];
__device__ float4        g_cls_boxes[BB * CC * MAXPC];

// ---------------------------------------------------------------------------
// Kernel A: decode boxes + per-anchor argmax mask
// ---------------------------------------------------------------------------
__global__ void decode_kernel(const float* __restrict__ deltas,
                              const float* __restrict__ labels,
                              const float* __restrict__ anchors) {
    int idx = blockIdx.x * blockDim.x + threadIdx.x;
    if (idx >= BB * NN) return;
    int n = idx % NN;

    float4 a = __ldg(((const float4*)anchors) + n);
    float4 d = __ldg(((const float4*)deltas) + idx);
    // variances
    d.x *= 0.1f; d.y *= 0.1f; d.z *= 0.2f; d.w *= 0.2f;

    float ah  = a.z - a.x;
    float aw  = a.w - a.y;
    float acy = a.x + 0.5f * ah;
    float acx = a.y + 0.5f * aw;
    float cy  = d.x * ah + acy;
    float cx  = d.y * aw + acx;
    float h   = expf(d.z) * ah;
    float w   = expf(d.w) * aw;

    g_boxes[idx] = make_float4(cy - 0.5f * h, cx - 0.5f * w,
                               cy + 0.5f * h, cx + 0.5f * w);

    // argmax over 21 classes (first-occurrence ties, like jnp.argmax)
    const float* lr = labels + (size_t)idx * CC;
    float best = lr[0];
    int   bi   = 0;
#pragma unroll
    for (int c = 1; c < CC; c++) {
        float v = lr[c];
        if (v > best) { best = v; bi = c; }
    }
    g_mask[idx] = (bi != 0) ? 1 : 0;
}

// ---------------------------------------------------------------------------
// IoU, exactly mirroring the reference fp32 formula
// ---------------------------------------------------------------------------
__device__ __forceinline__ float iou_f(float4 A, float4 B2) {
    float areaA = (A.z - A.x) * (A.w - A.y);
    float areaB = (B2.z - B2.x) * (B2.w - B2.y);
    float ih = fminf(A.z, B2.z) - fmaxf(A.x, B2.x); ih = fmaxf(ih, 0.0f);
    float iw = fminf(A.w, B2.w) - fmaxf(A.y, B2.y); iw = fmaxf(iw, 0.0f);
    float inter = ih * iw;
    return inter / (areaA + areaB - inter + 1e-8f);
}

// ---------------------------------------------------------------------------
// Kernel B: per-(b,c) exact top-200 select + greedy NMS + first-20 output
// One block (256 threads) per (b,c). 1344 blocks total.
// ---------------------------------------------------------------------------
__global__ __launch_bounds__(256) void nms_kernel(const float* __restrict__ labels) {
    const int b   = blockIdx.x / CC;
    const int c   = blockIdx.x % CC;
    const int tid = threadIdx.x;

    __shared__ int                hist[1024];
    __shared__ int                coarse[256];
    __shared__ unsigned long long keys[512];
    __shared__ float4             sbox[KCAND];
    __shared__ float              sscore[KCAND];
    __shared__ unsigned char      ssup[KCAND];
    __shared__ int                s_count, s_cut, s_kc, s_brk;

    for (int i = tid; i < 1024; i += 256) hist[i] = 0;
    if (tid == 0) { s_count = 0; s_kc = 0; s_brk = 0; }
    __syncthreads();

    const float*         Lb = labels + (size_t)b * NN * CC + c;
    const unsigned char* Mb = g_mask + b * NN;

    // Pass 1: histogram of masked positive scores
    for (int n = tid; n < NN; n += 256) {
        if (Mb[n]) {
            float s = Lb[(size_t)n * CC];
            if (s > 0.0f) {
                int bin = (int)(s * 1024.0f);
                bin = min(bin, 1023);
                atomicAdd(&hist[bin], 1);
            }
        }
    }
    __syncthreads();

    // Find cutoff bin for the top-200 (coarse 4x reduction, then drill down)
    {
        int b4 = tid * 4;
        coarse[tid] = hist[b4] + hist[b4 + 1] + hist[b4 + 2] + hist[b4 + 3];
    }
    __syncthreads();
    if (tid == 0) {
        int cum = 0, cut = 0;
        for (int cb = 255; cb >= 0; cb--) {
            int nc = cum + coarse[cb];
            if (nc >= KCAND) {
                int cum2 = cum;
                for (int bin = cb * 4 + 3; bin >= cb * 4; bin--) {
                    cum2 += hist[bin];
                    if (cum2 >= KCAND) { cut = bin; break; }
                }
                break;
            }
            cum = nc;
        }
        s_cut = cut;  // stays 0 if total < 200 -> take all positives
    }
    __syncthreads();
    int cut = s_cut;

    // Pass 2: collect candidates with bin >= cut
    for (int n = tid; n < NN; n += 256) {
        if (Mb[n]) {
            float s = Lb[(size_t)n * CC];
            if (s > 0.0f) {
                int bin = min((int)(s * 1024.0f), 1023);
                if (bin >= cut) {
                    int p = atomicAdd(&s_count, 1);
                    if (p < 512) {
                        // sort key: score desc, index asc on ties (jax-stable)
                        keys[p] = ((unsigned long long)__float_as_uint(s) << 32)
                                  | (unsigned)(~(unsigned)n);
                    }
                }
            }
        }
    }
    __syncthreads();
    int M = min(s_count, 512);
    for (int i = M + tid; i < 512; i += 256) keys[i] = 0ULL;
    __syncthreads();

    // Bitonic sort 512 keys descending (256 threads, 2 elems/thread)
    for (int k = 2; k <= 512; k <<= 1) {
        for (int j = k >> 1; j > 0; j >>= 1) {
            for (int i = tid; i < 512; i += 256) {
                int ixj = i ^ j;
                if (ixj > i) {
                    unsigned long long A = keys[i], Bk = keys[ixj];
                    bool descBlock = ((i & k) == 0);
                    if (descBlock ? (A < Bk) : (A > Bk)) {
                        keys[i] = Bk; keys[ixj] = A;
                    }
                }
            }
            __syncthreads();
        }
    }

    // Load top-200 candidates into smem
    if (tid < KCAND) {
        unsigned long long kk = keys[tid];
        float s = __uint_as_float((unsigned)(kk >> 32));
        sscore[tid] = s;
        ssup[tid]   = 0;
        float4 bx = make_float4(0.f, 0.f, 0.f, 0.f);
        if (s > 0.0f) {
            unsigned n = ~(unsigned)kk;
            bx = g_boxes[b * NN + n];
        }
        sbox[tid] = bx;
    }
    __syncthreads();

    const int outbase = (b * CC + c) * MAXPC;

    // Serial greedy NMS with early exit after 20 keeps (later keeps are
    // irrelevant to the first-20 output and cannot affect earlier decisions).
    for (int i = 0; i < KCAND; i++) {
        if (tid == 0) {
            int   kc = s_kc;
            float si = sscore[i];
            if (si <= 0.5f || kc >= MAXPC) {
                s_brk = 1;                       // stop: all later are smaller
            } else if (!ssup[i]) {
                g_cls_scores[outbase + kc] = si; // kept, emit in order
                g_cls_boxes[outbase + kc]  = sbox[i];
                s_kc  = kc + 1;
                s_brk = 2;                       // kept -> suppress pass
            } else {
                s_brk = 0;                       // suppressed, skip
            }
        }
        __syncthreads();
        int st = s_brk;
        if (st == 1) break;
        if (st == 2 && tid > i && tid < KCAND && !ssup[tid]) {
            if (iou_f(sbox[i], sbox[tid]) > 0.5f) ssup[tid] = 1;
        }
        __syncthreads();
    }

    __syncthreads();
    if (tid < MAXPC && tid >= s_kc) {
        g_cls_scores[outbase + tid] = 0.0f;
        g_cls_boxes[outbase + tid]  = make_float4(0.f, 0.f, 0.f, 0.f);
    }
}

// ---------------------------------------------------------------------------
// Kernel C: per-batch merge of 21*20 = 420 entries -> top-20 overall
// ---------------------------------------------------------------------------
__global__ __launch_bounds__(256) void merge_kernel(float* __restrict__ out) {
    const int b   = blockIdx.x;
    const int tid = threadIdx.x;
    __shared__ unsigned long long keys[512];

    for (int i = tid; i < 512; i += 256) {
        unsigned long long kk = 0ULL;
        if (i < CC * MAXPC) {
            float s = g_cls_scores[b * CC * MAXPC + i];
            kk = ((unsigned long long)__float_as_uint(s) << 32)
                 | (unsigned)(~(unsigned)i);
        }
        keys[i] = kk;
    }
    __syncthreads();

    for (int k = 2; k <= 512; k <<= 1) {
        for (int j = k >> 1; j > 0; j >>= 1) {
            for (int i = tid; i < 512; i += 256) {
                int ixj = i ^ j;
                if (ixj > i) {
                    unsigned long long A = keys[i], Bk = keys[ixj];
                    bool descBlock = ((i & k) == 0);
                    if (descBlock ? (A < Bk) : (A > Bk)) {
                        keys[i] = Bk; keys[ixj] = A;
                    }
                }
            }
            __syncthreads();
        }
    }

    if (tid < MAXTOT) {
        unsigned long long kk = keys[tid];
        float s   = __uint_as_float((unsigned)(kk >> 32));
        float val = s;                     // top_vals returned unmasked
        float4 bx = make_float4(0.f, 0.f, 0.f, 0.f);
        float lab = 0.0f;
        if (s > 0.0f) {
            unsigned fi = ~(unsigned)kk;   // flat index in [0, 420)
            bx = g_cls_boxes[b * CC * MAXPC + fi];
            bx.x = fminf(fmaxf(bx.x, 0.0f), 1.0f);
            bx.y = fminf(fmaxf(bx.y, 0.0f), 1.0f);
            bx.z = fminf(fmaxf(bx.z, 0.0f), 1.0f);
            bx.w = fminf(fmaxf(bx.w, 0.0f), 1.0f);
            lab = (float)(fi / MAXPC);
        }
        // Output layout: boxes [B,20,4] | vals [B,20] | labels [B,20]
        float* ob = out + (size_t)b * MAXTOT * 4;
        float* ov = out + (size_t)BB * MAXTOT * 4 + (size_t)b * MAXTOT;
        float* ol = out + (size_t)BB * MAXTOT * 4 + (size_t)BB * MAXTOT
                        + (size_t)b * MAXTOT;
        ob[tid * 4 + 0] = bx.x;
        ob[tid * 4 + 1] = bx.y;
        ob[tid * 4 + 2] = bx.z;
        ob[tid * 4 + 3] = bx.w;
        ov[tid] = val;
        ol[tid] = lab;
    }
}

// ---------------------------------------------------------------------------
extern "C" void kernel_launch(void* const* d_in, const int* in_sizes, int n_in,
                              void* d_out, int out_size) {
    const float* deltas  = (const float*)d_in[0];  // (64, 8732, 4)
    const float* labels  = (const float*)d_in[1];  // (64, 8732, 21)
    const float* anchors = (const float*)d_in[2];  // (8732, 4)
    float* out = (float*)d_out;

    int total = BB * NN;
    decode_kernel<<<(total + 255) / 256, 256>>>(deltas, labels, anchors);
    nms_kernel<<<BB * CC, 256>>>(labels);
    merge_kernel<<<BB, 256>>>(out);
}

// round 3
// speedup vs baseline: 1.2943x; 1.2943x over previous
#include <cuda_runtime.h>
#include <math.h>

// Problem constants
#define BB 64
#define NN 8732
#define CC 21
#define KCAND 200
#define MAXPC 20
#define MAXTOT 20

#define TILE 64
#define NTILES ((NN + TILE - 1) / TILE)   // 137

// Scratch (static device globals: allowed; no runtime allocation)
__device__ float4        g_boxes[BB * NN];                    // decoded boxes
__device__ float         g_scoresT[(size_t)BB * CC * NN];     // masked scores, [b][c][n]
__device__ float         g_cls_scores[BB * CC * MAXPC];
__device__ float4        g_cls_boxes[BB * CC * MAXPC];

// ---------------------------------------------------------------------------
// Kernel A: decode boxes + argmax mask + transposed masked-score write
// Block = 256 threads handles TILE=64 anchors of one batch.
// ---------------------------------------------------------------------------
__global__ __launch_bounds__(256) void decode_kernel(
        const float* __restrict__ deltas,
        const float* __restrict__ labels,
        const float* __restrict__ anchors) {
    const int b    = blockIdx.x / NTILES;
    const int tile = blockIdx.x % NTILES;
    const int n0   = tile * TILE;
    const int cnt  = min(TILE, NN - n0);
    const int tid  = threadIdx.x;

    __shared__ float         sl[TILE * CC];
    __shared__ unsigned char sm[TILE];

    // Coalesced load of the label tile (cnt*21 contiguous floats)
    const float* Lb  = labels + ((size_t)b * NN + n0) * CC;
    const int    tot = cnt * CC;
    for (int i = tid; i < tot; i += 256) sl[i] = Lb[i];
    __syncthreads();

    if (tid < cnt) {
        // argmax over 21 classes (first-occurrence ties, like jnp.argmax)
        const float* r = sl + tid * CC;
        float best = r[0];
        int   bi   = 0;
#pragma unroll
        for (int c = 1; c < CC; c++) {
            float v = r[c];
            if (v > best) { best = v; bi = c; }
        }
        sm[tid] = (bi != 0) ? 1 : 0;

        // decode box
        const int n = n0 + tid;
        float4 a = __ldg(((const float4*)anchors) + n);
        float4 d = __ldg(((const float4*)deltas) + (size_t)b * NN + n);
        d.x *= 0.1f; d.y *= 0.1f; d.z *= 0.2f; d.w *= 0.2f;

        float ah  = a.z - a.x;
        float aw  = a.w - a.y;
        float acy = a.x + 0.5f * ah;
        float acx = a.y + 0.5f * aw;
        float cy  = d.x * ah + acy;
        float cx  = d.y * aw + acx;
        float h   = expf(d.z) * ah;
        float w   = expf(d.w) * aw;

        g_boxes[(size_t)b * NN + n] = make_float4(cy - 0.5f * h, cx - 0.5f * w,
                                                  cy + 0.5f * h, cx + 0.5f * w);
    }
    __syncthreads();

    // Transposed masked-score write: coalesced over anchor index i
    for (int idx = tid; idx < CC * TILE; idx += 256) {
        const int c = idx / TILE;
        const int i = idx % TILE;
        if (i < cnt) {
            float s = sm[i] ? sl[i * CC + c] : 0.0f;
            g_scoresT[((size_t)b * CC + c) * NN + n0 + i] = s;
        }
    }
}

// ---------------------------------------------------------------------------
// IoU, exactly mirroring the reference fp32 formula
// ---------------------------------------------------------------------------
__device__ __forceinline__ float iou_f(float4 A, float4 B2) {
    float areaA = (A.z - A.x) * (A.w - A.y);
    float areaB = (B2.z - B2.x) * (B2.w - B2.y);
    float ih = fminf(A.z, B2.z) - fmaxf(A.x, B2.x); ih = fmaxf(ih, 0.0f);
    float iw = fminf(A.w, B2.w) - fmaxf(A.y, B2.y); iw = fmaxf(iw, 0.0f);
    float inter = ih * iw;
    return inter / (areaA + areaB - inter + 1e-8f);
}

// ---------------------------------------------------------------------------
// Kernel B: per-(b,c) exact top-200 select + greedy NMS + first-20 output
// One block (256 threads) per (b,c). 1344 blocks. Streams a contiguous
// 35KB score row twice (2nd pass L1/L2 resident).
// ---------------------------------------------------------------------------
__global__ __launch_bounds__(256) void nms_kernel() {
    const int b   = blockIdx.x / CC;
    const int c   = blockIdx.x % CC;
    const int tid = threadIdx.x;

    __shared__ int                hist[1024];
    __shared__ int                coarse[256];
    __shared__ unsigned long long keys[512];
    __shared__ float4             sbox[KCAND];
    __shared__ float              sscore[KCAND];
    __shared__ unsigned char      ssup[KCAND];
    __shared__ int                s_count, s_cut, s_kc, s_brk;

    for (int i = tid; i < 1024; i += 256) hist[i] = 0;
    if (tid == 0) { s_count = 0; s_kc = 0; s_brk = 0; }
    __syncthreads();

    const float4* S4 = (const float4*)(g_scoresT + ((size_t)b * CC + c) * NN);

    // Pass 1: histogram of positive masked scores (coalesced float4 stream)
    for (int i = tid; i < NN / 4; i += 256) {
        float4 v = S4[i];
        float ss[4] = { v.x, v.y, v.z, v.w };
#pragma unroll
        for (int k = 0; k < 4; k++) {
            float s = ss[k];
            if (s > 0.0f) {
                int bin = min((int)(s * 1024.0f), 1023);
                atomicAdd(&hist[bin], 1);
            }
        }
    }
    __syncthreads();

    // Find cutoff bin for the top-200 (coarse 4x reduction, then drill down)
    {
        int b4 = tid * 4;
        coarse[tid] = hist[b4] + hist[b4 + 1] + hist[b4 + 2] + hist[b4 + 3];
    }
    __syncthreads();
    if (tid == 0) {
        int cum = 0, cut = 0;
        for (int cb = 255; cb >= 0; cb--) {
            int nc = cum + coarse[cb];
            if (nc >= KCAND) {
                int cum2 = cum;
                for (int bin = cb * 4 + 3; bin >= cb * 4; bin--) {
                    cum2 += hist[bin];
                    if (cum2 >= KCAND) { cut = bin; break; }
                }
                break;
            }
            cum = nc;
        }
        s_cut = cut;  // stays 0 if total < 200 -> take all positives
    }
    __syncthreads();
    const int cut = s_cut;

    // Pass 2: collect candidates with bin >= cut (row is L1/L2 resident now)
    for (int i = tid; i < NN / 4; i += 256) {
        float4 v = S4[i];
        float ss[4] = { v.x, v.y, v.z, v.w };
#pragma unroll
        for (int k = 0; k < 4; k++) {
            float s = ss[k];
            if (s > 0.0f) {
                int bin = min((int)(s * 1024.0f), 1023);
                if (bin >= cut) {
                    int p = atomicAdd(&s_count, 1);
                    if (p < 512) {
                        unsigned n = (unsigned)(i * 4 + k);
                        // key: score desc, index asc on ties (jax-stable)
                        keys[p] = ((unsigned long long)__float_as_uint(s) << 32)
                                  | (unsigned)(~n);
                    }
                }
            }
        }
    }
    __syncthreads();
    int M = min(s_count, 512);
    for (int i = M + tid; i < 512; i += 256) keys[i] = 0ULL;
    __syncthreads();

    // Bitonic sort 512 keys descending
    for (int k = 2; k <= 512; k <<= 1) {
        for (int j = k >> 1; j > 0; j >>= 1) {
            for (int i = tid; i < 512; i += 256) {
                int ixj = i ^ j;
                if (ixj > i) {
                    unsigned long long A = keys[i], Bk = keys[ixj];
                    bool descBlock = ((i & k) == 0);
                    if (descBlock ? (A < Bk) : (A > Bk)) {
                        keys[i] = Bk; keys[ixj] = A;
                    }
                }
            }
            __syncthreads();
        }
    }

    // Load top-200 candidates into smem
    if (tid < KCAND) {
        unsigned long long kk = keys[tid];
        float s = __uint_as_float((unsigned)(kk >> 32));
        sscore[tid] = s;
        ssup[tid]   = 0;
        float4 bx = make_float4(0.f, 0.f, 0.f, 0.f);
        if (s > 0.0f) {
            unsigned n = ~(unsigned)kk;
            bx = g_boxes[(size_t)b * NN + n];
        }
        sbox[tid] = bx;
    }
    __syncthreads();

    const int outbase = (b * CC + c) * MAXPC;

    // Serial greedy NMS with early exit after 20 keeps
    for (int i = 0; i < KCAND; i++) {
        if (tid == 0) {
            int   kc = s_kc;
            float si = sscore[i];
            if (si <= 0.5f || kc >= MAXPC) {
                s_brk = 1;                        // stop: all later are smaller
            } else if (!ssup[i]) {
                g_cls_scores[outbase + kc] = si;  // kept, emit in order
                g_cls_boxes[outbase + kc]  = sbox[i];
                s_kc  = kc + 1;
                s_brk = 2;                        // kept -> suppress pass
            } else {
                s_brk = 0;                        // suppressed, skip
            }
        }
        __syncthreads();
        int st = s_brk;
        if (st == 1) break;
        if (st == 2 && tid > i && tid < KCAND && !ssup[tid]) {
            if (iou_f(sbox[i], sbox[tid]) > 0.5f) ssup[tid] = 1;
        }
        __syncthreads();
    }

    __syncthreads();
    if (tid < MAXPC && tid >= s_kc) {
        g_cls_scores[outbase + tid] = 0.0f;
        g_cls_boxes[outbase + tid]  = make_float4(0.f, 0.f, 0.f, 0.f);
    }
}

// ---------------------------------------------------------------------------
// Kernel C: per-batch merge of 21*20 = 420 entries -> top-20 overall
// ---------------------------------------------------------------------------
__global__ __launch_bounds__(256) void merge_kernel(float* __restrict__ out) {
    const int b   = blockIdx.x;
    const int tid = threadIdx.x;
    __shared__ unsigned long long keys[512];

    for (int i = tid; i < 512; i += 256) {
        unsigned long long kk = 0ULL;
        if (i < CC * MAXPC) {
            float s = g_cls_scores[b * CC * MAXPC + i];
            kk = ((unsigned long long)__float_as_uint(s) << 32)
                 | (unsigned)(~(unsigned)i);
        }
        keys[i] = kk;
    }
    __syncthreads();

    for (int k = 2; k <= 512; k <<= 1) {
        for (int j = k >> 1; j > 0; j >>= 1) {
            for (int i = tid; i < 512; i += 256) {
                int ixj = i ^ j;
                if (ixj > i) {
                    unsigned long long A = keys[i], Bk = keys[ixj];
                    bool descBlock = ((i & k) == 0);
                    if (descBlock ? (A < Bk) : (A > Bk)) {
                        keys[i] = Bk; keys[ixj] = A;
                    }
                }
            }
            __syncthreads();
        }
    }

    if (tid < MAXTOT) {
        unsigned long long kk = keys[tid];
        float s   = __uint_as_float((unsigned)(kk >> 32));
        float val = s;                     // top_vals returned unmasked
        float4 bx = make_float4(0.f, 0.f, 0.f, 0.f);
        float lab = 0.0f;
        if (s > 0.0f) {
            unsigned fi = ~(unsigned)kk;   // flat index in [0, 420)
            bx = g_cls_boxes[b * CC * MAXPC + fi];
            bx.x = fminf(fmaxf(bx.x, 0.0f), 1.0f);
            bx.y = fminf(fmaxf(bx.y, 0.0f), 1.0f);
            bx.z = fminf(fmaxf(bx.z, 0.0f), 1.0f);
            bx.w = fminf(fmaxf(bx.w, 0.0f), 1.0f);
            lab = (float)(fi / MAXPC);
        }
        // Output layout: boxes [B,20,4] | vals [B,20] | labels [B,20]
        float* ob = out + (size_t)b * MAXTOT * 4;
        float* ov = out + (size_t)BB * MAXTOT * 4 + (size_t)b * MAXTOT;
        float* ol = out + (size_t)BB * MAXTOT * 4 + (size_t)BB * MAXTOT
                        + (size_t)b * MAXTOT;
        ob[tid * 4 + 0] = bx.x;
        ob[tid * 4 + 1] = bx.y;
        ob[tid * 4 + 2] = bx.z;
        ob[tid * 4 + 3] = bx.w;
        ov[tid] = val;
        ol[tid] = lab;
    }
}

// ---------------------------------------------------------------------------
extern "C" void kernel_launch(void* const* d_in, const int* in_sizes, int n_in,
                              void* d_out, int out_size) {
    const float* deltas  = (const float*)d_in[0];  // (64, 8732, 4)
    const float* labels  = (const float*)d_in[1];  // (64, 8732, 21)
    const float* anchors = (const float*)d_in[2];  // (8732, 4)
    float* out = (float*)d_out;

    decode_kernel<<<BB * NTILES, 256>>>(deltas, labels, anchors);
    nms_kernel<<<BB * CC, 256>>>();
    merge_kernel<<<BB, 256>>>(out);
}